// round 2
// baseline (speedup 1.0000x reference)
#include <cuda_runtime.h>
#include <cuda_bf16.h>

// Problem constants (fixed by the dataset)
#define MAXN 100000
#define MAXE 3200000
#define INC1 64
#define HIDC 128
#define OUTC2 64

// ---------------- device scratch (no allocations allowed) ----------------
__device__ float g_buf_g[MAXN * HIDC];   // g1 (dinv*h1), later reused for g2
__device__ float g_buf_o[MAXN * HIDC];   // relu(layer1 output)
__device__ int   g_rowptr[MAXN + 1];
__device__ int   g_cursor[MAXN];
__device__ int   g_col[MAXE];            // CSR col (src ids), sorted by dst
__device__ float g_dinv[MAXN];
__device__ int   g_cnt[MAXN];

// ---------------- CSR build ----------------
__global__ void zero_cnt_kernel(int n) {
    int i = blockIdx.x * blockDim.x + threadIdx.x;
    if (i < n) g_cnt[i] = 0;
}

__global__ void count_kernel(const int* __restrict__ dst, int E) {
    int e = blockIdx.x * blockDim.x + threadIdx.x;
    if (e < E) atomicAdd(&g_cnt[dst[e]], 1);
}

// One-block scan over n counts -> exclusive row_ptr, cursor copy, dinv.
// Degree = cnt + 1 (self loop), always > 0.
__global__ void scan_kernel(int n) {
    __shared__ int sums[1024];
    int t = threadIdx.x;
    int chunk = (n + 1023) >> 10;
    int beg = t * chunk;
    int end = beg + chunk; if (end > n) end = n;
    int s = 0;
    if (beg < n) for (int i = beg; i < end; i++) s += g_cnt[i];
    sums[t] = s;
    __syncthreads();
    // Hillis-Steele inclusive scan
    for (int off = 1; off < 1024; off <<= 1) {
        int v = sums[t];
        int add = (t >= off) ? sums[t - off] : 0;
        __syncthreads();
        sums[t] = v + add;
        __syncthreads();
    }
    int run = (t == 0) ? 0 : sums[t - 1];
    if (beg < n) {
        for (int i = beg; i < end; i++) {
            g_rowptr[i] = run;
            g_cursor[i] = run;
            g_dinv[i]   = rsqrtf((float)(g_cnt[i] + 1));
            run += g_cnt[i];
        }
    }
    if (t == 1023) g_rowptr[n] = sums[1023];
}

__global__ void fill_kernel(const int* __restrict__ src,
                            const int* __restrict__ dst, int E) {
    int e = blockIdx.x * blockDim.x + threadIdx.x;
    if (e < E) {
        int d = dst[e];
        int pos = atomicAdd(&g_cursor[d], 1);
        g_col[pos] = src[e];
    }
}

// ---------------- GEMM + dinv scale: G[i,:] = dinv[i] * (X[i,:] @ W) ----------------
template <int INC, int OUTC, int RY, int RPB>
__global__ void __launch_bounds__(OUTC * RY)
gemm_scale_kernel(const float* __restrict__ X, const float* __restrict__ W,
                  float* __restrict__ G, int n) {
    __shared__ float Ws[INC * OUTC];
    __shared__ float Xs[RY][INC];
    const int tx = threadIdx.x;        // output channel
    const int ty = threadIdx.y;        // row slot
    const int tid = ty * OUTC + tx;
    const int nthr = OUTC * RY;
    for (int i = tid; i < INC * OUTC; i += nthr) Ws[i] = W[i];
    __syncthreads();
    const int base = blockIdx.x * RPB;
    for (int r0 = 0; r0 < RPB; r0 += RY) {
        // cooperative load RY rows of X
        for (int i = tid; i < RY * INC; i += nthr) {
            int rr = base + r0 + i / INC;
            Xs[i / INC][i % INC] = (rr < n) ? X[rr * INC + (i % INC)] : 0.f;
        }
        __syncthreads();
        int row = base + r0 + ty;
        if (row < n) {
            float acc = 0.f;
#pragma unroll
            for (int k = 0; k < INC; k++)
                acc += Xs[ty][k] * Ws[k * OUTC + tx];
            G[row * OUTC + tx] = g_dinv[row] * acc;
        }
        __syncthreads();
    }
}

// ---------------- Aggregation (CSR gather), one warp per node ----------------
// C=128: lane holds float4 (32 lanes * 4 = 128). Includes self-loop term (acc init),
// epilogue: relu(dinv*acc + b).
__global__ void __launch_bounds__(256)
agg128_kernel(const float* __restrict__ G, const float* __restrict__ b,
              float* __restrict__ O, int n) {
    int warp = (blockIdx.x * blockDim.x + threadIdx.x) >> 5;
    int lane = threadIdx.x & 31;
    if (warp >= n) return;
    const int d = warp;
    const float4* __restrict__ Gv = (const float4*)G;
    float4 acc = Gv[d * 32 + lane];              // self loop (s = d)
    int e = g_rowptr[d];
    const int end = g_rowptr[d + 1];
    for (; e + 4 <= end; e += 4) {
        int s0 = g_col[e];
        int s1 = g_col[e + 1];
        int s2 = g_col[e + 2];
        int s3 = g_col[e + 3];
        float4 a0 = Gv[s0 * 32 + lane];
        float4 a1 = Gv[s1 * 32 + lane];
        float4 a2 = Gv[s2 * 32 + lane];
        float4 a3 = Gv[s3 * 32 + lane];
        acc.x += a0.x; acc.y += a0.y; acc.z += a0.z; acc.w += a0.w;
        acc.x += a1.x; acc.y += a1.y; acc.z += a1.z; acc.w += a1.w;
        acc.x += a2.x; acc.y += a2.y; acc.z += a2.z; acc.w += a2.w;
        acc.x += a3.x; acc.y += a3.y; acc.z += a3.z; acc.w += a3.w;
    }
    for (; e < end; e++) {
        int s = g_col[e];
        float4 a = Gv[s * 32 + lane];
        acc.x += a.x; acc.y += a.y; acc.z += a.z; acc.w += a.w;
    }
    const float di = g_dinv[d];
    float4 bi = ((const float4*)b)[lane];
    float4 o;
    o.x = fmaxf(di * acc.x + bi.x, 0.f);
    o.y = fmaxf(di * acc.y + bi.y, 0.f);
    o.z = fmaxf(di * acc.z + bi.z, 0.f);
    o.w = fmaxf(di * acc.w + bi.w, 0.f);
    ((float4*)O)[d * 32 + lane] = o;
}

// C=64: lane holds float2 (32 lanes * 2 = 64). No relu, writes final output.
__global__ void __launch_bounds__(256)
agg64_kernel(const float* __restrict__ G, const float* __restrict__ b,
             float* __restrict__ O, int n) {
    int warp = (blockIdx.x * blockDim.x + threadIdx.x) >> 5;
    int lane = threadIdx.x & 31;
    if (warp >= n) return;
    const int d = warp;
    const float2* __restrict__ Gv = (const float2*)G;
    float2 acc = Gv[d * 32 + lane];              // self loop
    int e = g_rowptr[d];
    const int end = g_rowptr[d + 1];
    for (; e + 4 <= end; e += 4) {
        int s0 = g_col[e];
        int s1 = g_col[e + 1];
        int s2 = g_col[e + 2];
        int s3 = g_col[e + 3];
        float2 a0 = Gv[s0 * 32 + lane];
        float2 a1 = Gv[s1 * 32 + lane];
        float2 a2 = Gv[s2 * 32 + lane];
        float2 a3 = Gv[s3 * 32 + lane];
        acc.x += a0.x; acc.y += a0.y;
        acc.x += a1.x; acc.y += a1.y;
        acc.x += a2.x; acc.y += a2.y;
        acc.x += a3.x; acc.y += a3.y;
    }
    for (; e < end; e++) {
        int s = g_col[e];
        float2 a = Gv[s * 32 + lane];
        acc.x += a.x; acc.y += a.y;
    }
    const float di = g_dinv[d];
    float2 bi = ((const float2*)b)[lane];
    float2 o;
    o.x = di * acc.x + bi.x;
    o.y = di * acc.y + bi.y;
    ((float2*)O)[d * 32 + lane] = o;
}

// ---------------- launch ----------------
extern "C" void kernel_launch(void* const* d_in, const int* in_sizes, int n_in,
                              void* d_out, int out_size) {
    const float* x  = (const float*)d_in[0];
    const int*   ei = (const int*)d_in[1];     // int32! (JAX x64-disabled truncates int64)
    const float* W1 = (const float*)d_in[2];
    const float* b1 = (const float*)d_in[3];
    const float* W2 = (const float*)d_in[4];
    const float* b2 = (const float*)d_in[5];
    float* out = (float*)d_out;

    const int n = in_sizes[0] / INC1;     // 100000
    const int E = in_sizes[1] / 2;        // 3200000
    const int* src = ei;
    const int* dst = ei + E;

    // buffer aliases (device globals)
    float* d_g = nullptr; cudaGetSymbolAddress((void**)&d_g, g_buf_g);
    float* d_o = nullptr; cudaGetSymbolAddress((void**)&d_o, g_buf_o);

    // 1) CSR build (shared by both layers)
    zero_cnt_kernel<<<(n + 255) / 256, 256>>>(n);
    count_kernel<<<(E + 255) / 256, 256>>>(dst, E);
    scan_kernel<<<1, 1024>>>(n);
    fill_kernel<<<(E + 255) / 256, 256>>>(src, dst, E);

    // 2) layer 1: g1 = dinv * (x @ W1)
    gemm_scale_kernel<INC1, HIDC, 2, 64><<<(n + 63) / 64, dim3(HIDC, 2)>>>(x, W1, d_g, n);
    // 3) aggregate + relu -> buf_o
    agg128_kernel<<<(n * 32 + 255) / 256, 256>>>(d_g, b1, d_o, n);
    // 4) layer 2: g2 = dinv * (buf_o @ W2)  (reuse g buffer)
    gemm_scale_kernel<HIDC, OUTC2, 4, 64><<<(n + 63) / 64, dim3(OUTC2, 4)>>>(d_o, W2, d_g, n);
    // 5) aggregate -> final output
    agg64_kernel<<<(n * 32 + 255) / 256, 256>>>(d_g, b2, out, n);
}